// round 13
// baseline (speedup 1.0000x reference)
#include <cuda_runtime.h>
#include <cuda_bf16.h>
#include <cstdint>

// Problem dims
#define B_N    4096
#define U_DIM  256
#define D_DIM  64
#define KIN    320
#define H_DIM  8192
#define ORD    4096
#define Y_DIM  256
#define DELTA_F 0.1f

#define GSPLITS 28            // grid 5*2*28 = 280 CTAs = one clean 2-CTA/SM wave
#define STAGE_BYTES 49152
#define FY_STAGE 32768

// ---------------- scratch (static device globals) ----------------
__device__ uint4 g_Chi4[Y_DIM * H_DIM / 8];   // C' hi bf16 [256][8192]
__device__ uint4 g_Clo4[Y_DIM * H_DIM / 8];
__device__ uint4 g_BwTh4[KIN * H_DIM / 8];    // Bw^T hi bf16 [320][8192]
__device__ uint4 g_BwTl4[KIN * H_DIM / 8];
__device__ uint4 g_uduh4[B_N * KIN / 8];      // [du|u] hi bf16 [4096][320]
__device__ uint4 g_udul4[B_N * KIN / 8];
__device__ float g_Gpart[GSPLITS][Y_DIM * KIN];
__device__ uint4 g_Ghi4[Y_DIM * KIN / 8];     // G hi bf16 [256][320]
__device__ uint4 g_Glo4[Y_DIM * KIN / 8];
__device__ float g_p[ORD], g_q[ORD], g_rec[H_DIM];
__device__ float g_y0p[Y_DIM * 4], g_y0[Y_DIM];

// ---------------- helpers ----------------
__device__ __forceinline__ uint32_t smem_u32(const void* p) {
    uint32_t a;
    asm("{ .reg .u64 t; cvta.to.shared.u64 t, %1; cvt.u32.u64 %0, t; }"
        : "=r"(a) : "l"(p));
    return a;
}
#define SW128(o) ((o) ^ (((o) >> 3) & 0x70))

__device__ __forceinline__ void ldsm_x4(uint32_t* r, uint32_t addr) {
    asm volatile("ldmatrix.sync.aligned.m8n8.x4.shared.b16 {%0,%1,%2,%3}, [%4];"
                 : "=r"(r[0]), "=r"(r[1]), "=r"(r[2]), "=r"(r[3]) : "r"(addr));
}
__device__ __forceinline__ void mma16816(float* c, const uint32_t* a, const uint32_t* b) {
    asm volatile(
        "mma.sync.aligned.m16n8k16.row.col.f32.bf16.bf16.f32 "
        "{%0,%1,%2,%3}, {%4,%5,%6,%7}, {%8,%9}, {%0,%1,%2,%3};"
        : "+f"(c[0]), "+f"(c[1]), "+f"(c[2]), "+f"(c[3])
        : "r"(a[0]), "r"(a[1]), "r"(a[2]), "r"(a[3]), "r"(b[0]), "r"(b[1]));
}
__device__ __forceinline__ void cpa16(uint32_t s, const void* g) {
    asm volatile("cp.async.cg.shared.global [%0], [%1], 16;" :: "r"(s), "l"(g) : "memory");
}
#define CPA_COMMIT() asm volatile("cp.async.commit_group;" ::: "memory")

__device__ __forceinline__ void split1(float v, unsigned short& h, unsigned short& l) {
    __nv_bfloat16 hb = __float2bfloat16(v);
    float r = v - __bfloat162float(hb);
    __nv_bfloat16 lb = __float2bfloat16(r);
    h = *reinterpret_cast<unsigned short*>(&hb);
    l = *reinterpret_cast<unsigned short*>(&lb);
}
__device__ __forceinline__ uint32_t pkw(unsigned short a, unsigned short b) {
    return (uint32_t)a | ((uint32_t)b << 16);
}

// ---------------- kernel 0: rotation coefficients ----------------
__global__ void coef_kernel(const float* __restrict__ om, const float* __restrict__ h) {
    int j = blockIdx.x * blockDim.x + threadIdx.x;
    if (j >= ORD) return;
    float w = om[j];
    float s, c;
    sincosf(w * DELTA_F, &s, &c);
    float inv = 1.0f / w;
    g_p[j] = s * inv;
    g_q[j] = (c - 1.0f) * inv;
    float h0 = h[2 * j], h1 = h[2 * j + 1];
    g_rec[2 * j]     =  c * h0 + s * h1;
    g_rec[2 * j + 1] = -s * h0 + c * h1;
}

// ---------------- kernel 1: merged prep (C' fold + y0) and Bw split ----------------
// blocks [0,1024): prep, block = (m<<2)|quarter.  blocks [1024,1664): bwsplit.
__global__ __launch_bounds__(256) void prepsplit_kernel(const float* __restrict__ Cw,
                                                        const float* __restrict__ Bw) {
    __shared__ __align__(16) char shmem[64 * 65 * 4];
    int bid = blockIdx.x;
    int t = threadIdx.x;
    if (bid < 1024) {
        int m = bid >> 2;
        int jb = (bid & 3) * 1024 + t * 4;
        const float* crow = Cw + (size_t)m * H_DIM;
        float4 c0 = *(const float4*)(crow + 2 * jb);
        float4 c1 = *(const float4*)(crow + 2 * jb + 4);
        float4 pv = *(const float4*)(g_p + jb);
        float4 qv = *(const float4*)(g_q + jb);
        float4 r0 = *(const float4*)(g_rec + 2 * jb);
        float4 r1 = *(const float4*)(g_rec + 2 * jb + 4);
        float y0acc = c0.x * r0.x + c0.y * r0.y + c0.z * r0.z + c0.w * r0.w +
                      c1.x * r1.x + c1.y * r1.y + c1.z * r1.z + c1.w * r1.w;
        float o[8];
        o[0] =  c0.x * pv.x + c0.y * qv.x;  o[1] = -c0.x * qv.x + c0.y * pv.x;
        o[2] =  c0.z * pv.y + c0.w * qv.y;  o[3] = -c0.z * qv.y + c0.w * pv.y;
        o[4] =  c1.x * pv.z + c1.y * qv.z;  o[5] = -c1.x * qv.z + c1.y * pv.z;
        o[6] =  c1.z * pv.w + c1.w * qv.w;  o[7] = -c1.z * qv.w + c1.w * pv.w;
        unsigned short h[8], l[8];
#pragma unroll
        for (int i = 0; i < 8; i++) split1(o[i], h[i], l[i]);
        size_t vi = ((size_t)m * H_DIM + 2 * jb) / 8;
        g_Chi4[vi] = make_uint4(pkw(h[0], h[1]), pkw(h[2], h[3]), pkw(h[4], h[5]), pkw(h[6], h[7]));
        g_Clo4[vi] = make_uint4(pkw(l[0], l[1]), pkw(l[2], l[3]), pkw(l[4], l[5]), pkw(l[6], l[7]));
        float* red = (float*)shmem;
        red[t] = y0acc;
        __syncthreads();
        for (int off = 128; off > 0; off >>= 1) {
            if (t < off) red[t] += red[t + off];
            __syncthreads();
        }
        if (t == 0) g_y0p[m * 4 + (bid & 3)] = red[0];
    } else {
        int b = bid - 1024;
        int k0 = (b & 127) * 64, n0 = (b >> 7) * 64;
        float (*tile)[65] = (float(*)[65])shmem;
#pragma unroll
        for (int i = 0; i < 4; i++) {
            int idx = t + i * 256;
            int r = idx >> 4, c4 = idx & 15;
            float4 v = *(const float4*)&Bw[(size_t)(k0 + r) * KIN + n0 + c4 * 4];
            tile[r][c4 * 4 + 0] = v.x;
            tile[r][c4 * 4 + 1] = v.y;
            tile[r][c4 * 4 + 2] = v.z;
            tile[r][c4 * 4 + 3] = v.w;
        }
        __syncthreads();
#pragma unroll
        for (int i = 0; i < 2; i++) {
            int idx = t + i * 256;
            int nr = idx >> 3, q = idx & 7;
            unsigned short h[8], l[8];
#pragma unroll
            for (int e = 0; e < 8; e++) split1(tile[q * 8 + e][nr], h[e], l[e]);
            size_t vi = ((size_t)(n0 + nr) * H_DIM + k0 + q * 8) / 8;
            g_BwTh4[vi] = make_uint4(pkw(h[0], h[1]), pkw(h[2], h[3]), pkw(h[4], h[5]), pkw(h[6], h[7]));
            g_BwTl4[vi] = make_uint4(pkw(l[0], l[1]), pkw(l[2], l[3]), pkw(l[4], l[5]), pkw(l[6], l[7]));
        }
    }
}

// ---------------- kernel 2: udu concat + split (coalesced uint4 stores) ----------------
__global__ __launch_bounds__(256) void udusplit_kernel(const float* __restrict__ u,
                                                       const float* __restrict__ du) {
    int idx8 = blockIdx.x * 256 + threadIdx.x;
    if (idx8 >= B_N * KIN / 8) return;
    int row = idx8 / (KIN / 8);
    int col = (idx8 % (KIN / 8)) * 8;
    float4 v0, v1;
    if (col < D_DIM) {
        v0 = *(const float4*)&du[(size_t)row * D_DIM + col];
        v1 = *(const float4*)&du[(size_t)row * D_DIM + col + 4];
    } else {
        v0 = *(const float4*)&u[(size_t)row * U_DIM + col - D_DIM];
        v1 = *(const float4*)&u[(size_t)row * U_DIM + col - D_DIM + 4];
    }
    unsigned short h[8], l[8];
    split1(v0.x, h[0], l[0]); split1(v0.y, h[1], l[1]);
    split1(v0.z, h[2], l[2]); split1(v0.w, h[3], l[3]);
    split1(v1.x, h[4], l[4]); split1(v1.y, h[5], l[5]);
    split1(v1.z, h[6], l[6]); split1(v1.w, h[7], l[7]);
    g_uduh4[idx8] = make_uint4(pkw(h[0], h[1]), pkw(h[2], h[3]), pkw(h[4], h[5]), pkw(h[6], h[7]));
    g_udul4[idx8] = make_uint4(pkw(l[0], l[1]), pkw(l[2], l[3]), pkw(l[4], l[5]), pkw(l[6], l[7]));
}

// ---------------- shared mma core: 3-term split, fragment sharing ----------------
// TERM-MAJOR mma order: all independent accumulators between same-acc reuse
// (reuse distance 2*MT*NB mmas) — hides HMMA RAW latency.
template <int MT, int NB>
__device__ __forceinline__ void mma3(int lane, int wm, int wn, float acc[][2 * NB][4],
                                     uint32_t ah, uint32_t al,
                                     uint32_t bh, uint32_t bl) {
#pragma unroll
    for (int s = 0; s < 4; s++) {
        uint32_t Ah[MT][4], Al[MT][4], Bh[NB][4], Bl[NB][4];
#pragma unroll
        for (int mt = 0; mt < MT; mt++) {
            int row = wm * (16 * MT) + mt * 16 + (lane & 15);
            int cb = s * 32 + ((lane >> 4) << 4);
            uint32_t o = SW128((uint32_t)(row * 128 + cb));
            ldsm_x4(Ah[mt], ah + o);
            ldsm_x4(Al[mt], al + o);
        }
#pragma unroll
        for (int nb = 0; nb < NB; nb++) {
            int row = wn * (16 * NB) + nb * 16 + (lane & 7) + ((lane & 16) ? 8 : 0);
            int cb = s * 32 + ((lane & 8) ? 16 : 0);
            uint32_t o = SW128((uint32_t)(row * 128 + cb));
            ldsm_x4(Bh[nb], bh + o);
            ldsm_x4(Bl[nb], bl + o);
        }
        // term 1: Ah * Bh
#pragma unroll
        for (int mt = 0; mt < MT; mt++)
#pragma unroll
            for (int nt = 0; nt < 2 * NB; nt++)
                mma16816(acc[mt][nt], Ah[mt], &Bh[nt >> 1][(nt & 1) * 2]);
        // term 2: Ah * Bl
#pragma unroll
        for (int mt = 0; mt < MT; mt++)
#pragma unroll
            for (int nt = 0; nt < 2 * NB; nt++)
                mma16816(acc[mt][nt], Ah[mt], &Bl[nt >> 1][(nt & 1) * 2]);
        // term 3: Al * Bh
#pragma unroll
        for (int mt = 0; mt < MT; mt++)
#pragma unroll
            for (int nt = 0; nt < 2 * NB; nt++)
                mma16816(acc[mt][nt], Al[mt], &Bh[nt >> 1][(nt & 1) * 2]);
    }
}

// ---------------- gemmG tile prefetch (cp.async, 256 threads) ----------------
__device__ __forceinline__ void gemmG_load_stage(uint32_t sb, int t, int m0, int n0, int ktg) {
#pragma unroll
    for (int i = 0; i < 4; i++) {
        int idx = t + i * 256;
        int row = idx >> 3, q = idx & 7;
        uint32_t off = SW128((uint32_t)(row * 128 + q * 16));
        size_t src = (size_t)(m0 + row) * (H_DIM / 8) + (size_t)ktg * 8 + q;
        cpa16(sb + off,         &g_Chi4[src]);
        cpa16(sb + 16384 + off, &g_Clo4[src]);
    }
#pragma unroll
    for (int i = 0; i < 2; i++) {
        int idx = t + i * 256;
        int row = idx >> 3, q = idx & 7;
        uint32_t off = SW128((uint32_t)(row * 128 + q * 16));
        size_t src = (size_t)(n0 + row) * (H_DIM / 8) + (size_t)ktg * 8 + q;
        cpa16(sb + 32768 + off, &g_BwTh4[src]);
        cpa16(sb + 40960 + off, &g_BwTl4[src]);
    }
}

// ---------------- kernel 3: gemmG, single wave (280 CTAs) ----------------
// grid (5 n, 2 m, 28 splits), 256 thr, warp tile 32x32, 96KB dyn smem, 2 CTA/SM
__global__ __launch_bounds__(256, 2) void gemmG_kernel() {
    extern __shared__ __align__(128) char dsm[];
    uint32_t sb = smem_u32(dsm);
    int t = threadIdx.x, lane = t & 31, w = t >> 5;
    int wm = w >> 1, wn = w & 1;
    int n0 = blockIdx.x * 64, m0 = blockIdx.y * 128, sp = blockIdx.z;
    int kt0 = (128 * sp) / GSPLITS, kt1 = (128 * (sp + 1)) / GSPLITS;
    float acc[2][4][4];
#pragma unroll
    for (int mt = 0; mt < 2; mt++)
#pragma unroll
        for (int nt = 0; nt < 4; nt++)
#pragma unroll
            for (int e = 0; e < 4; e++) acc[mt][nt][e] = 0.0f;

    gemmG_load_stage(sb, t, m0, n0, kt0);
    CPA_COMMIT();
#pragma unroll 1
    for (int kt = kt0; kt < kt1; kt++) {
        __syncthreads();
        if (kt + 1 < kt1) {
            gemmG_load_stage(sb + ((kt - kt0 + 1) & 1) * STAGE_BYTES, t, m0, n0, kt + 1);
            CPA_COMMIT();
            asm volatile("cp.async.wait_group 1;" ::: "memory");
        } else {
            asm volatile("cp.async.wait_group 0;" ::: "memory");
        }
        __syncthreads();
        uint32_t ss = sb + ((kt - kt0) & 1) * STAGE_BYTES;
        mma3<2, 2>(lane, wm, wn, acc, ss, ss + 16384, ss + 32768, ss + 40960);
    }
    float* out = g_Gpart[sp];
    int gid = lane >> 2, tig = lane & 3;
#pragma unroll
    for (int mt = 0; mt < 2; mt++)
#pragma unroll
        for (int nt = 0; nt < 4; nt++) {
            int r0 = m0 + wm * 32 + mt * 16 + gid;
            int c = n0 + wn * 32 + nt * 8 + tig * 2;
            *(float2*)&out[(size_t)r0 * KIN + c] =
                make_float2(acc[mt][nt][0], acc[mt][nt][1]);
            *(float2*)&out[(size_t)(r0 + 8) * KIN + c] =
                make_float2(acc[mt][nt][2], acc[mt][nt][3]);
        }
}

// ---------------- kernel 4: split-K reduce -> G bf16 hi/lo + y0 ----------------
__global__ void reduceG_kernel() {
    int idx = blockIdx.x * blockDim.x + threadIdx.x;
    if (idx < Y_DIM * KIN) {
        float s = 0.0f;
#pragma unroll
        for (int p = 0; p < GSPLITS; p++) s += g_Gpart[p][idx];
        unsigned short hh, ll;
        split1(s, hh, ll);
        ((unsigned short*)g_Ghi4)[idx] = hh;
        ((unsigned short*)g_Glo4)[idx] = ll;
    }
    if (idx < Y_DIM) {
        g_y0[idx] = (g_y0p[idx * 4 + 0] + g_y0p[idx * 4 + 1]) +
                    (g_y0p[idx * 4 + 2] + g_y0p[idx * 4 + 3]);
    }
}

// ---------------- finalY tile prefetch (cp.async, 128 threads) ----------------
__device__ __forceinline__ void finalY_load_stage(uint32_t sb, int t, int m0, int n0, int kt) {
#pragma unroll
    for (int i = 0; i < 4; i++) {
        int idx = t + i * 128;
        int row = idx >> 3, q = idx & 7;
        uint32_t off = SW128((uint32_t)(row * 128 + q * 16));
        size_t sA = (size_t)(m0 + row) * (KIN / 8) + (size_t)kt * 8 + q;
        size_t sB = (size_t)(n0 + row) * (KIN / 8) + (size_t)kt * 8 + q;
        cpa16(sb + off,         &g_uduh4[sA]);
        cpa16(sb + 8192 + off,  &g_udul4[sA]);
        cpa16(sb + 16384 + off, &g_Ghi4[sB]);
        cpa16(sb + 24576 + off, &g_Glo4[sB]);
    }
}

// ---------------- kernel 5: finalY = y0 + udu @ G^T, double-buffered ----------------
// grid (4 n, 64 m) = 256 CTAs, 128 thr (4 warps, warp tile 32x32), 64KB dyn smem
__global__ __launch_bounds__(128) void finalY_kernel(float* __restrict__ y) {
    extern __shared__ __align__(128) char dsm[];
    uint32_t sb = smem_u32(dsm);
    int t = threadIdx.x, lane = t & 31, w = t >> 5;
    int wm = w >> 1, wn = w & 1;
    int n0 = blockIdx.x * 64, m0 = blockIdx.y * 64;
    float acc[2][4][4];
#pragma unroll
    for (int mt = 0; mt < 2; mt++)
#pragma unroll
        for (int nt = 0; nt < 4; nt++)
#pragma unroll
            for (int e = 0; e < 4; e++) acc[mt][nt][e] = 0.0f;

    finalY_load_stage(sb, t, m0, n0, 0);
    CPA_COMMIT();
#pragma unroll 1
    for (int kt = 0; kt < KIN / 64; kt++) {
        __syncthreads();
        if (kt + 1 < KIN / 64) {
            finalY_load_stage(sb + ((kt + 1) & 1) * FY_STAGE, t, m0, n0, kt + 1);
            CPA_COMMIT();
            asm volatile("cp.async.wait_group 1;" ::: "memory");
        } else {
            asm volatile("cp.async.wait_group 0;" ::: "memory");
        }
        __syncthreads();
        uint32_t ss = sb + (kt & 1) * FY_STAGE;
        mma3<2, 2>(lane, wm, wn, acc, ss, ss + 8192, ss + 16384, ss + 24576);
    }
    int gid = lane >> 2, tig = lane & 3;
#pragma unroll
    for (int mt = 0; mt < 2; mt++)
#pragma unroll
        for (int nt = 0; nt < 4; nt++) {
            int r0 = m0 + wm * 32 + mt * 16 + gid;
            int c = n0 + wn * 32 + nt * 8 + tig * 2;
            float2 y0v = *(const float2*)&g_y0[c];
            *(float2*)&y[(size_t)r0 * Y_DIM + c] =
                make_float2(acc[mt][nt][0] + y0v.x, acc[mt][nt][1] + y0v.y);
            *(float2*)&y[(size_t)(r0 + 8) * Y_DIM + c] =
                make_float2(acc[mt][nt][2] + y0v.x, acc[mt][nt][3] + y0v.y);
        }
}

// ---------------- launch ----------------
extern "C" void kernel_launch(void* const* d_in, const int* in_sizes, int n_in,
                              void* d_out, int out_size) {
    const float *u = nullptr, *du = nullptr, *h = nullptr, *om = nullptr,
                *Bw = nullptr, *Cw = nullptr;
    for (int i = 0; i < n_in; i++) {
        switch (in_sizes[i]) {
            case B_N * U_DIM:   u  = (const float*)d_in[i]; break;
            case B_N * D_DIM:   du = (const float*)d_in[i]; break;
            case H_DIM:         h  = (const float*)d_in[i]; break;
            case ORD:           om = (const float*)d_in[i]; break;
            case H_DIM * KIN:   Bw = (const float*)d_in[i]; break;
            case Y_DIM * H_DIM: Cw = (const float*)d_in[i]; break;
            default: break;
        }
    }
    if (!u || !du || !h || !om || !Bw || !Cw) {
        u  = (const float*)d_in[0];
        du = (const float*)d_in[1];
        h  = (const float*)d_in[2];
        om = (const float*)d_in[3];
        Bw = (const float*)d_in[4];
        Cw = (const float*)d_in[5];
    }
    float* y = (float*)d_out;

    cudaFuncSetAttribute(gemmG_kernel,
                         cudaFuncAttributeMaxDynamicSharedMemorySize, 2 * STAGE_BYTES);
    cudaFuncSetAttribute(finalY_kernel,
                         cudaFuncAttributeMaxDynamicSharedMemorySize, 2 * FY_STAGE);

    coef_kernel<<<ORD / 256, 256>>>(om, h);
    prepsplit_kernel<<<1664, 256>>>(Cw, Bw);
    udusplit_kernel<<<(B_N * KIN / 8 + 255) / 256, 256>>>(u, du);
    gemmG_kernel<<<dim3(5, 2, GSPLITS), 256, 2 * STAGE_BYTES>>>();
    reduceG_kernel<<<(Y_DIM * KIN + 255) / 256, 256>>>();
    finalY_kernel<<<dim3(Y_DIM / 64, B_N / 64), 128, 2 * FY_STAGE>>>(y);
}

// round 14
// speedup vs baseline: 1.1119x; 1.1119x over previous
#include <cuda_runtime.h>
#include <cuda_bf16.h>
#include <cstdint>

// Problem dims
#define B_N    4096
#define U_DIM  256
#define D_DIM  64
#define KIN    320
#define H_DIM  8192
#define ORD    4096
#define Y_DIM  256
#define DELTA_F 0.1f

#define GSPLITS 28            // grid 5*2*28 = 280 CTAs = one clean 2-CTA/SM wave
#define STAGE_BYTES 49152
#define FY_STAGE 24576

// ---------------- scratch (static device globals) ----------------
__device__ uint4 g_Chi4[Y_DIM * H_DIM / 8];   // C' hi bf16 [256][8192]
__device__ uint4 g_Clo4[Y_DIM * H_DIM / 8];
__device__ uint4 g_BwTh4[KIN * H_DIM / 8];    // Bw^T hi bf16 [320][8192]
__device__ uint4 g_BwTl4[KIN * H_DIM / 8];
__device__ uint4 g_uduh4[B_N * KIN / 8];      // [du|u] hi bf16 [4096][320]
__device__ uint4 g_udul4[B_N * KIN / 8];
__device__ float g_Gpart[GSPLITS][Y_DIM * KIN];
__device__ uint4 g_Ghi4[Y_DIM * KIN / 8];     // G hi bf16 [256][320]
__device__ uint4 g_Glo4[Y_DIM * KIN / 8];
__device__ float g_y0p[Y_DIM * 4], g_y0[Y_DIM];

// ---------------- helpers ----------------
__device__ __forceinline__ uint32_t smem_u32(const void* p) {
    uint32_t a;
    asm("{ .reg .u64 t; cvta.to.shared.u64 t, %1; cvt.u32.u64 %0, t; }"
        : "=r"(a) : "l"(p));
    return a;
}
#define SW128(o) ((o) ^ (((o) >> 3) & 0x70))

__device__ __forceinline__ void ldsm_x4(uint32_t* r, uint32_t addr) {
    asm volatile("ldmatrix.sync.aligned.m8n8.x4.shared.b16 {%0,%1,%2,%3}, [%4];"
                 : "=r"(r[0]), "=r"(r[1]), "=r"(r[2]), "=r"(r[3]) : "r"(addr));
}
__device__ __forceinline__ void mma16816(float* c, const uint32_t* a, const uint32_t* b) {
    asm volatile(
        "mma.sync.aligned.m16n8k16.row.col.f32.bf16.bf16.f32 "
        "{%0,%1,%2,%3}, {%4,%5,%6,%7}, {%8,%9}, {%0,%1,%2,%3};"
        : "+f"(c[0]), "+f"(c[1]), "+f"(c[2]), "+f"(c[3])
        : "r"(a[0]), "r"(a[1]), "r"(a[2]), "r"(a[3]), "r"(b[0]), "r"(b[1]));
}
__device__ __forceinline__ void cpa16(uint32_t s, const void* g) {
    asm volatile("cp.async.cg.shared.global [%0], [%1], 16;" :: "r"(s), "l"(g) : "memory");
}
#define CPA_COMMIT() asm volatile("cp.async.commit_group;" ::: "memory")

__device__ __forceinline__ void split1(float v, unsigned short& h, unsigned short& l) {
    __nv_bfloat16 hb = __float2bfloat16(v);
    float r = v - __bfloat162float(hb);
    __nv_bfloat16 lb = __float2bfloat16(r);
    h = *reinterpret_cast<unsigned short*>(&hb);
    l = *reinterpret_cast<unsigned short*>(&lb);
}
__device__ __forceinline__ uint32_t pkw(unsigned short a, unsigned short b) {
    return (uint32_t)a | ((uint32_t)b << 16);
}

// ---------------- kernel 1: unified prepare ----------------
// blocks [0,1024): C' fold + y0 partials (coef inlined)
// blocks [1024,1664): Bw transpose + split
// blocks [1664,2304): udu concat + split
__global__ __launch_bounds__(256) void prepare_kernel(const float* __restrict__ Cw,
                                                      const float* __restrict__ Bw,
                                                      const float* __restrict__ u,
                                                      const float* __restrict__ du,
                                                      const float* __restrict__ om,
                                                      const float* __restrict__ hst) {
    __shared__ __align__(16) char shmem[64 * 65 * 4];
    int bid = blockIdx.x;
    int t = threadIdx.x;
    if (bid < 1024) {
        int m = bid >> 2;
        int jb = (bid & 3) * 1024 + t * 4;      // 4 pairs = 8 elems
        // inline coef: p,q,rec for our 4 pairs
        float4 wv = *(const float4*)(om + jb);
        float p[4], q[4], rc[8];
        float4 h0 = *(const float4*)(hst + 2 * jb);
        float4 h1 = *(const float4*)(hst + 2 * jb + 4);
        float hh[8] = {h0.x, h0.y, h0.z, h0.w, h1.x, h1.y, h1.z, h1.w};
        float wa[4] = {wv.x, wv.y, wv.z, wv.w};
#pragma unroll
        for (int i = 0; i < 4; i++) {
            float s, c;
            sincosf(wa[i] * DELTA_F, &s, &c);
            float inv = 1.0f / wa[i];
            p[i] = s * inv;
            q[i] = (c - 1.0f) * inv;
            rc[2 * i]     =  c * hh[2 * i] + s * hh[2 * i + 1];
            rc[2 * i + 1] = -s * hh[2 * i] + c * hh[2 * i + 1];
        }
        const float* crow = Cw + (size_t)m * H_DIM;
        float4 c0 = *(const float4*)(crow + 2 * jb);
        float4 c1 = *(const float4*)(crow + 2 * jb + 4);
        float cc[8] = {c0.x, c0.y, c0.z, c0.w, c1.x, c1.y, c1.z, c1.w};
        float y0acc = 0.0f;
        float o[8];
#pragma unroll
        for (int i = 0; i < 4; i++) {
            y0acc += cc[2 * i] * rc[2 * i] + cc[2 * i + 1] * rc[2 * i + 1];
            o[2 * i]     =  cc[2 * i] * p[i] + cc[2 * i + 1] * q[i];
            o[2 * i + 1] = -cc[2 * i] * q[i] + cc[2 * i + 1] * p[i];
        }
        unsigned short h[8], l[8];
#pragma unroll
        for (int i = 0; i < 8; i++) split1(o[i], h[i], l[i]);
        size_t vi = ((size_t)m * H_DIM + 2 * jb) / 8;
        g_Chi4[vi] = make_uint4(pkw(h[0], h[1]), pkw(h[2], h[3]), pkw(h[4], h[5]), pkw(h[6], h[7]));
        g_Clo4[vi] = make_uint4(pkw(l[0], l[1]), pkw(l[2], l[3]), pkw(l[4], l[5]), pkw(l[6], l[7]));
        float* red = (float*)shmem;
        red[t] = y0acc;
        __syncthreads();
        for (int off = 128; off > 0; off >>= 1) {
            if (t < off) red[t] += red[t + off];
            __syncthreads();
        }
        if (t == 0) g_y0p[m * 4 + (bid & 3)] = red[0];
    } else if (bid < 1664) {
        int b = bid - 1024;
        int k0 = (b & 127) * 64, n0 = (b >> 7) * 64;
        float (*tile)[65] = (float(*)[65])shmem;
#pragma unroll
        for (int i = 0; i < 4; i++) {
            int idx = t + i * 256;
            int r = idx >> 4, c4 = idx & 15;
            float4 v = *(const float4*)&Bw[(size_t)(k0 + r) * KIN + n0 + c4 * 4];
            tile[r][c4 * 4 + 0] = v.x;
            tile[r][c4 * 4 + 1] = v.y;
            tile[r][c4 * 4 + 2] = v.z;
            tile[r][c4 * 4 + 3] = v.w;
        }
        __syncthreads();
#pragma unroll
        for (int i = 0; i < 2; i++) {
            int idx = t + i * 256;
            int nr = idx >> 3, q = idx & 7;
            unsigned short h[8], l[8];
#pragma unroll
            for (int e = 0; e < 8; e++) split1(tile[q * 8 + e][nr], h[e], l[e]);
            size_t vi = ((size_t)(n0 + nr) * H_DIM + k0 + q * 8) / 8;
            g_BwTh4[vi] = make_uint4(pkw(h[0], h[1]), pkw(h[2], h[3]), pkw(h[4], h[5]), pkw(h[6], h[7]));
            g_BwTl4[vi] = make_uint4(pkw(l[0], l[1]), pkw(l[2], l[3]), pkw(l[4], l[5]), pkw(l[6], l[7]));
        }
    } else {
        int idx8 = (bid - 1664) * 256 + t;
        if (idx8 >= B_N * KIN / 8) return;
        int row = idx8 / (KIN / 8);
        int col = (idx8 % (KIN / 8)) * 8;
        float4 v0, v1;
        if (col < D_DIM) {
            v0 = *(const float4*)&du[(size_t)row * D_DIM + col];
            v1 = *(const float4*)&du[(size_t)row * D_DIM + col + 4];
        } else {
            v0 = *(const float4*)&u[(size_t)row * U_DIM + col - D_DIM];
            v1 = *(const float4*)&u[(size_t)row * U_DIM + col - D_DIM + 4];
        }
        unsigned short h[8], l[8];
        split1(v0.x, h[0], l[0]); split1(v0.y, h[1], l[1]);
        split1(v0.z, h[2], l[2]); split1(v0.w, h[3], l[3]);
        split1(v1.x, h[4], l[4]); split1(v1.y, h[5], l[5]);
        split1(v1.z, h[6], l[6]); split1(v1.w, h[7], l[7]);
        g_uduh4[idx8] = make_uint4(pkw(h[0], h[1]), pkw(h[2], h[3]), pkw(h[4], h[5]), pkw(h[6], h[7]));
        g_udul4[idx8] = make_uint4(pkw(l[0], l[1]), pkw(l[2], l[3]), pkw(l[4], l[5]), pkw(l[6], l[7]));
    }
}

// ---------------- shared mma core: 3-term split, term-major, fragment sharing ----------------
template <int MT, int NB>
__device__ __forceinline__ void mma3(int lane, int wm, int wn, float acc[][2 * NB][4],
                                     uint32_t ah, uint32_t al,
                                     uint32_t bh, uint32_t bl) {
#pragma unroll
    for (int s = 0; s < 4; s++) {
        uint32_t Ah[MT][4], Al[MT][4], Bh[NB][4], Bl[NB][4];
#pragma unroll
        for (int mt = 0; mt < MT; mt++) {
            int row = wm * (16 * MT) + mt * 16 + (lane & 15);
            int cb = s * 32 + ((lane >> 4) << 4);
            uint32_t o = SW128((uint32_t)(row * 128 + cb));
            ldsm_x4(Ah[mt], ah + o);
            ldsm_x4(Al[mt], al + o);
        }
#pragma unroll
        for (int nb = 0; nb < NB; nb++) {
            int row = wn * (16 * NB) + nb * 16 + (lane & 7) + ((lane & 16) ? 8 : 0);
            int cb = s * 32 + ((lane & 8) ? 16 : 0);
            uint32_t o = SW128((uint32_t)(row * 128 + cb));
            ldsm_x4(Bh[nb], bh + o);
            ldsm_x4(Bl[nb], bl + o);
        }
#pragma unroll
        for (int mt = 0; mt < MT; mt++)
#pragma unroll
            for (int nt = 0; nt < 2 * NB; nt++)
                mma16816(acc[mt][nt], Ah[mt], &Bh[nt >> 1][(nt & 1) * 2]);
#pragma unroll
        for (int mt = 0; mt < MT; mt++)
#pragma unroll
            for (int nt = 0; nt < 2 * NB; nt++)
                mma16816(acc[mt][nt], Ah[mt], &Bl[nt >> 1][(nt & 1) * 2]);
#pragma unroll
        for (int mt = 0; mt < MT; mt++)
#pragma unroll
            for (int nt = 0; nt < 2 * NB; nt++)
                mma16816(acc[mt][nt], Al[mt], &Bh[nt >> 1][(nt & 1) * 2]);
    }
}

// ---------------- gemmG tile prefetch (cp.async, 256 threads) ----------------
__device__ __forceinline__ void gemmG_load_stage(uint32_t sb, int t, int m0, int n0, int ktg) {
#pragma unroll
    for (int i = 0; i < 4; i++) {
        int idx = t + i * 256;
        int row = idx >> 3, q = idx & 7;
        uint32_t off = SW128((uint32_t)(row * 128 + q * 16));
        size_t src = (size_t)(m0 + row) * (H_DIM / 8) + (size_t)ktg * 8 + q;
        cpa16(sb + off,         &g_Chi4[src]);
        cpa16(sb + 16384 + off, &g_Clo4[src]);
    }
#pragma unroll
    for (int i = 0; i < 2; i++) {
        int idx = t + i * 256;
        int row = idx >> 3, q = idx & 7;
        uint32_t off = SW128((uint32_t)(row * 128 + q * 16));
        size_t src = (size_t)(n0 + row) * (H_DIM / 8) + (size_t)ktg * 8 + q;
        cpa16(sb + 32768 + off, &g_BwTh4[src]);
        cpa16(sb + 40960 + off, &g_BwTl4[src]);
    }
}

// ---------------- kernel 2: gemmG, single wave (280 CTAs) ----------------
__global__ __launch_bounds__(256, 2) void gemmG_kernel() {
    extern __shared__ __align__(128) char dsm[];
    uint32_t sb = smem_u32(dsm);
    int t = threadIdx.x, lane = t & 31, w = t >> 5;
    int wm = w >> 1, wn = w & 1;
    int n0 = blockIdx.x * 64, m0 = blockIdx.y * 128, sp = blockIdx.z;
    int kt0 = (128 * sp) / GSPLITS, kt1 = (128 * (sp + 1)) / GSPLITS;
    float acc[2][4][4];
#pragma unroll
    for (int mt = 0; mt < 2; mt++)
#pragma unroll
        for (int nt = 0; nt < 4; nt++)
#pragma unroll
            for (int e = 0; e < 4; e++) acc[mt][nt][e] = 0.0f;

    gemmG_load_stage(sb, t, m0, n0, kt0);
    CPA_COMMIT();
#pragma unroll 1
    for (int kt = kt0; kt < kt1; kt++) {
        __syncthreads();
        if (kt + 1 < kt1) {
            gemmG_load_stage(sb + ((kt - kt0 + 1) & 1) * STAGE_BYTES, t, m0, n0, kt + 1);
            CPA_COMMIT();
            asm volatile("cp.async.wait_group 1;" ::: "memory");
        } else {
            asm volatile("cp.async.wait_group 0;" ::: "memory");
        }
        __syncthreads();
        uint32_t ss = sb + ((kt - kt0) & 1) * STAGE_BYTES;
        mma3<2, 2>(lane, wm, wn, acc, ss, ss + 16384, ss + 32768, ss + 40960);
    }
    float* out = g_Gpart[sp];
    int gid = lane >> 2, tig = lane & 3;
#pragma unroll
    for (int mt = 0; mt < 2; mt++)
#pragma unroll
        for (int nt = 0; nt < 4; nt++) {
            int r0 = m0 + wm * 32 + mt * 16 + gid;
            int c = n0 + wn * 32 + nt * 8 + tig * 2;
            *(float2*)&out[(size_t)r0 * KIN + c] =
                make_float2(acc[mt][nt][0], acc[mt][nt][1]);
            *(float2*)&out[(size_t)(r0 + 8) * KIN + c] =
                make_float2(acc[mt][nt][2], acc[mt][nt][3]);
        }
}

// ---------------- kernel 3: split-K reduce -> G bf16 hi/lo + y0 ----------------
__global__ void reduceG_kernel() {
    int idx = blockIdx.x * blockDim.x + threadIdx.x;
    if (idx < Y_DIM * KIN) {
        float s = 0.0f;
#pragma unroll
        for (int p = 0; p < GSPLITS; p++) s += g_Gpart[p][idx];
        unsigned short hh, ll;
        split1(s, hh, ll);
        ((unsigned short*)g_Ghi4)[idx] = hh;
        ((unsigned short*)g_Glo4)[idx] = ll;
    }
    if (idx < Y_DIM) {
        g_y0[idx] = (g_y0p[idx * 4 + 0] + g_y0p[idx * 4 + 1]) +
                    (g_y0p[idx * 4 + 2] + g_y0p[idx * 4 + 3]);
    }
}

// ---------------- finalY tile prefetch (cp.async, 128 threads) ----------------
// stage: AH [0,4K) AL [4K,8K) BH [8K,16K) BL [16K,24K)
__device__ __forceinline__ void finalY_load_stage(uint32_t sb, int t, int m0, int n0, int kt) {
#pragma unroll
    for (int i = 0; i < 2; i++) {
        int idx = t + i * 128;
        int row = idx >> 3, q = idx & 7;
        uint32_t off = SW128((uint32_t)(row * 128 + q * 16));
        size_t sA = (size_t)(m0 + row) * (KIN / 8) + (size_t)kt * 8 + q;
        cpa16(sb + off,        &g_uduh4[sA]);
        cpa16(sb + 4096 + off, &g_udul4[sA]);
    }
#pragma unroll
    for (int i = 0; i < 4; i++) {
        int idx = t + i * 128;
        int row = idx >> 3, q = idx & 7;
        uint32_t off = SW128((uint32_t)(row * 128 + q * 16));
        size_t sB = (size_t)(n0 + row) * (KIN / 8) + (size_t)kt * 8 + q;
        cpa16(sb + 8192 + off,  &g_Ghi4[sB]);
        cpa16(sb + 16384 + off, &g_Glo4[sB]);
    }
}

// ---------------- kernel 4: finalY = y0 + udu @ G^T, 512 CTAs, double-buffered ----------------
// grid (4 n, 128 m), 128 thr (4 warps, warp tile 16x32), CTA tile 32x64, 48KB dyn smem
__global__ __launch_bounds__(128) void finalY_kernel(float* __restrict__ y) {
    extern __shared__ __align__(128) char dsm[];
    uint32_t sb = smem_u32(dsm);
    int t = threadIdx.x, lane = t & 31, w = t >> 5;
    int wm = w >> 1, wn = w & 1;
    int n0 = blockIdx.x * 64, m0 = blockIdx.y * 32;
    float acc[1][4][4];
#pragma unroll
    for (int nt = 0; nt < 4; nt++)
#pragma unroll
        for (int e = 0; e < 4; e++) acc[0][nt][e] = 0.0f;

    finalY_load_stage(sb, t, m0, n0, 0);
    CPA_COMMIT();
#pragma unroll 1
    for (int kt = 0; kt < KIN / 64; kt++) {
        __syncthreads();
        if (kt + 1 < KIN / 64) {
            finalY_load_stage(sb + ((kt + 1) & 1) * FY_STAGE, t, m0, n0, kt + 1);
            CPA_COMMIT();
            asm volatile("cp.async.wait_group 1;" ::: "memory");
        } else {
            asm volatile("cp.async.wait_group 0;" ::: "memory");
        }
        __syncthreads();
        uint32_t ss = sb + (kt & 1) * FY_STAGE;
        mma3<1, 2>(lane, wm, wn, acc, ss, ss + 4096, ss + 8192, ss + 16384);
    }
    int gid = lane >> 2, tig = lane & 3;
#pragma unroll
    for (int nt = 0; nt < 4; nt++) {
        int r0 = m0 + wm * 16 + gid;
        int c = n0 + wn * 32 + nt * 8 + tig * 2;
        float2 y0v = *(const float2*)&g_y0[c];
        *(float2*)&y[(size_t)r0 * Y_DIM + c] =
            make_float2(acc[0][nt][0] + y0v.x, acc[0][nt][1] + y0v.y);
        *(float2*)&y[(size_t)(r0 + 8) * Y_DIM + c] =
            make_float2(acc[0][nt][2] + y0v.x, acc[0][nt][3] + y0v.y);
    }
}

// ---------------- launch ----------------
extern "C" void kernel_launch(void* const* d_in, const int* in_sizes, int n_in,
                              void* d_out, int out_size) {
    const float *u = nullptr, *du = nullptr, *h = nullptr, *om = nullptr,
                *Bw = nullptr, *Cw = nullptr;
    for (int i = 0; i < n_in; i++) {
        switch (in_sizes[i]) {
            case B_N * U_DIM:   u  = (const float*)d_in[i]; break;
            case B_N * D_DIM:   du = (const float*)d_in[i]; break;
            case H_DIM:         h  = (const float*)d_in[i]; break;
            case ORD:           om = (const float*)d_in[i]; break;
            case H_DIM * KIN:   Bw = (const float*)d_in[i]; break;
            case Y_DIM * H_DIM: Cw = (const float*)d_in[i]; break;
            default: break;
        }
    }
    if (!u || !du || !h || !om || !Bw || !Cw) {
        u  = (const float*)d_in[0];
        du = (const float*)d_in[1];
        h  = (const float*)d_in[2];
        om = (const float*)d_in[3];
        Bw = (const float*)d_in[4];
        Cw = (const float*)d_in[5];
    }
    float* y = (float*)d_out;

    cudaFuncSetAttribute(gemmG_kernel,
                         cudaFuncAttributeMaxDynamicSharedMemorySize, 2 * STAGE_BYTES);
    cudaFuncSetAttribute(finalY_kernel,
                         cudaFuncAttributeMaxDynamicSharedMemorySize, 2 * FY_STAGE);

    prepare_kernel<<<2304, 256>>>(Cw, Bw, u, du, om, h);
    gemmG_kernel<<<dim3(5, 2, GSPLITS), 256, 2 * STAGE_BYTES>>>();
    reduceG_kernel<<<(Y_DIM * KIN + 255) / 256, 256>>>();
    finalY_kernel<<<dim3(Y_DIM / 64, B_N / 32), 128, 2 * FY_STAGE>>>(y);
}

// round 15
// speedup vs baseline: 1.1303x; 1.0165x over previous
#include <cuda_runtime.h>
#include <cuda_bf16.h>
#include <cstdint>

// Problem dims
#define B_N    4096
#define U_DIM  256
#define D_DIM  64
#define KIN    320
#define H_DIM  8192
#define ORD    4096
#define Y_DIM  256
#define DELTA_F 0.1f

#define GSPLITS 28            // grid 5*2*28 = 280 CTAs = one clean 2-CTA/SM wave
#define STAGE_BYTES 49152
#define FY_STAGE 32768

// ---------------- scratch (static device globals) ----------------
__device__ uint4 g_Chi4[Y_DIM * H_DIM / 8];   // C' hi bf16 [256][8192]
__device__ uint4 g_Clo4[Y_DIM * H_DIM / 8];
__device__ uint4 g_BwTh4[KIN * H_DIM / 8];    // Bw^T hi bf16 [320][8192]
__device__ uint4 g_BwTl4[KIN * H_DIM / 8];
__device__ uint4 g_uduh4[B_N * KIN / 8];      // [du|u] hi bf16 [4096][320]
__device__ uint4 g_udul4[B_N * KIN / 8];
__device__ float g_Gpart[GSPLITS][Y_DIM * KIN];
__device__ uint4 g_Ghi4[Y_DIM * KIN / 8];     // G hi bf16 [256][320]
__device__ uint4 g_Glo4[Y_DIM * KIN / 8];
__device__ float g_y0p[Y_DIM * 4], g_y0[Y_DIM];

// ---------------- helpers ----------------
__device__ __forceinline__ uint32_t smem_u32(const void* p) {
    uint32_t a;
    asm("{ .reg .u64 t; cvta.to.shared.u64 t, %1; cvt.u32.u64 %0, t; }"
        : "=r"(a) : "l"(p));
    return a;
}
#define SW128(o) ((o) ^ (((o) >> 3) & 0x70))

__device__ __forceinline__ void ldsm_x4(uint32_t* r, uint32_t addr) {
    asm volatile("ldmatrix.sync.aligned.m8n8.x4.shared.b16 {%0,%1,%2,%3}, [%4];"
                 : "=r"(r[0]), "=r"(r[1]), "=r"(r[2]), "=r"(r[3]) : "r"(addr));
}
__device__ __forceinline__ void mma16816(float* c, const uint32_t* a, const uint32_t* b) {
    asm volatile(
        "mma.sync.aligned.m16n8k16.row.col.f32.bf16.bf16.f32 "
        "{%0,%1,%2,%3}, {%4,%5,%6,%7}, {%8,%9}, {%0,%1,%2,%3};"
        : "+f"(c[0]), "+f"(c[1]), "+f"(c[2]), "+f"(c[3])
        : "r"(a[0]), "r"(a[1]), "r"(a[2]), "r"(a[3]), "r"(b[0]), "r"(b[1]));
}
__device__ __forceinline__ void cpa16(uint32_t s, const void* g) {
    asm volatile("cp.async.cg.shared.global [%0], [%1], 16;" :: "r"(s), "l"(g) : "memory");
}
#define CPA_COMMIT() asm volatile("cp.async.commit_group;" ::: "memory")

__device__ __forceinline__ void split1(float v, unsigned short& h, unsigned short& l) {
    __nv_bfloat16 hb = __float2bfloat16(v);
    float r = v - __bfloat162float(hb);
    __nv_bfloat16 lb = __float2bfloat16(r);
    h = *reinterpret_cast<unsigned short*>(&hb);
    l = *reinterpret_cast<unsigned short*>(&lb);
}
__device__ __forceinline__ uint32_t pkw(unsigned short a, unsigned short b) {
    return (uint32_t)a | ((uint32_t)b << 16);
}

// ---------------- kernel 1: unified prepare ----------------
// blocks [0,1024): C' fold + y0 partials (coef inlined)
// blocks [1024,1664): Bw transpose + split
// blocks [1664,2304): udu concat + split
__global__ __launch_bounds__(256) void prepare_kernel(const float* __restrict__ Cw,
                                                      const float* __restrict__ Bw,
                                                      const float* __restrict__ u,
                                                      const float* __restrict__ du,
                                                      const float* __restrict__ om,
                                                      const float* __restrict__ hst) {
    __shared__ __align__(16) char shmem[64 * 65 * 4];
    int bid = blockIdx.x;
    int t = threadIdx.x;
    if (bid < 1024) {
        int m = bid >> 2;
        int jb = (bid & 3) * 1024 + t * 4;      // 4 pairs = 8 elems
        float4 wv = *(const float4*)(om + jb);
        float p[4], q[4], rc[8];
        float4 h0 = *(const float4*)(hst + 2 * jb);
        float4 h1 = *(const float4*)(hst + 2 * jb + 4);
        float hh[8] = {h0.x, h0.y, h0.z, h0.w, h1.x, h1.y, h1.z, h1.w};
        float wa[4] = {wv.x, wv.y, wv.z, wv.w};
#pragma unroll
        for (int i = 0; i < 4; i++) {
            float s, c;
            sincosf(wa[i] * DELTA_F, &s, &c);
            float inv = 1.0f / wa[i];
            p[i] = s * inv;
            q[i] = (c - 1.0f) * inv;
            rc[2 * i]     =  c * hh[2 * i] + s * hh[2 * i + 1];
            rc[2 * i + 1] = -s * hh[2 * i] + c * hh[2 * i + 1];
        }
        const float* crow = Cw + (size_t)m * H_DIM;
        float4 c0 = *(const float4*)(crow + 2 * jb);
        float4 c1 = *(const float4*)(crow + 2 * jb + 4);
        float cc[8] = {c0.x, c0.y, c0.z, c0.w, c1.x, c1.y, c1.z, c1.w};
        float y0acc = 0.0f;
        float o[8];
#pragma unroll
        for (int i = 0; i < 4; i++) {
            y0acc += cc[2 * i] * rc[2 * i] + cc[2 * i + 1] * rc[2 * i + 1];
            o[2 * i]     =  cc[2 * i] * p[i] + cc[2 * i + 1] * q[i];
            o[2 * i + 1] = -cc[2 * i] * q[i] + cc[2 * i + 1] * p[i];
        }
        unsigned short h[8], l[8];
#pragma unroll
        for (int i = 0; i < 8; i++) split1(o[i], h[i], l[i]);
        size_t vi = ((size_t)m * H_DIM + 2 * jb) / 8;
        g_Chi4[vi] = make_uint4(pkw(h[0], h[1]), pkw(h[2], h[3]), pkw(h[4], h[5]), pkw(h[6], h[7]));
        g_Clo4[vi] = make_uint4(pkw(l[0], l[1]), pkw(l[2], l[3]), pkw(l[4], l[5]), pkw(l[6], l[7]));
        float* red = (float*)shmem;
        red[t] = y0acc;
        __syncthreads();
        for (int off = 128; off > 0; off >>= 1) {
            if (t < off) red[t] += red[t + off];
            __syncthreads();
        }
        if (t == 0) g_y0p[m * 4 + (bid & 3)] = red[0];
    } else if (bid < 1664) {
        int b = bid - 1024;
        int k0 = (b & 127) * 64, n0 = (b >> 7) * 64;
        float (*tile)[65] = (float(*)[65])shmem;
#pragma unroll
        for (int i = 0; i < 4; i++) {
            int idx = t + i * 256;
            int r = idx >> 4, c4 = idx & 15;
            float4 v = *(const float4*)&Bw[(size_t)(k0 + r) * KIN + n0 + c4 * 4];
            tile[r][c4 * 4 + 0] = v.x;
            tile[r][c4 * 4 + 1] = v.y;
            tile[r][c4 * 4 + 2] = v.z;
            tile[r][c4 * 4 + 3] = v.w;
        }
        __syncthreads();
#pragma unroll
        for (int i = 0; i < 2; i++) {
            int idx = t + i * 256;
            int nr = idx >> 3, q = idx & 7;
            unsigned short h[8], l[8];
#pragma unroll
            for (int e = 0; e < 8; e++) split1(tile[q * 8 + e][nr], h[e], l[e]);
            size_t vi = ((size_t)(n0 + nr) * H_DIM + k0 + q * 8) / 8;
            g_BwTh4[vi] = make_uint4(pkw(h[0], h[1]), pkw(h[2], h[3]), pkw(h[4], h[5]), pkw(h[6], h[7]));
            g_BwTl4[vi] = make_uint4(pkw(l[0], l[1]), pkw(l[2], l[3]), pkw(l[4], l[5]), pkw(l[6], l[7]));
        }
    } else {
        int idx8 = (bid - 1664) * 256 + t;
        if (idx8 >= B_N * KIN / 8) return;
        int row = idx8 / (KIN / 8);
        int col = (idx8 % (KIN / 8)) * 8;
        float4 v0, v1;
        if (col < D_DIM) {
            v0 = *(const float4*)&du[(size_t)row * D_DIM + col];
            v1 = *(const float4*)&du[(size_t)row * D_DIM + col + 4];
        } else {
            v0 = *(const float4*)&u[(size_t)row * U_DIM + col - D_DIM];
            v1 = *(const float4*)&u[(size_t)row * U_DIM + col - D_DIM + 4];
        }
        unsigned short h[8], l[8];
        split1(v0.x, h[0], l[0]); split1(v0.y, h[1], l[1]);
        split1(v0.z, h[2], l[2]); split1(v0.w, h[3], l[3]);
        split1(v1.x, h[4], l[4]); split1(v1.y, h[5], l[5]);
        split1(v1.z, h[6], l[6]); split1(v1.w, h[7], l[7]);
        g_uduh4[idx8] = make_uint4(pkw(h[0], h[1]), pkw(h[2], h[3]), pkw(h[4], h[5]), pkw(h[6], h[7]));
        g_udul4[idx8] = make_uint4(pkw(l[0], l[1]), pkw(l[2], l[3]), pkw(l[4], l[5]), pkw(l[6], l[7]));
    }
}

// ---------------- shared mma core: 3-term split, term-major, fragment sharing ----------------
template <int MT, int NB>
__device__ __forceinline__ void mma3(int lane, int wm, int wn, float acc[][2 * NB][4],
                                     uint32_t ah, uint32_t al,
                                     uint32_t bh, uint32_t bl) {
#pragma unroll
    for (int s = 0; s < 4; s++) {
        uint32_t Ah[MT][4], Al[MT][4], Bh[NB][4], Bl[NB][4];
#pragma unroll
        for (int mt = 0; mt < MT; mt++) {
            int row = wm * (16 * MT) + mt * 16 + (lane & 15);
            int cb = s * 32 + ((lane >> 4) << 4);
            uint32_t o = SW128((uint32_t)(row * 128 + cb));
            ldsm_x4(Ah[mt], ah + o);
            ldsm_x4(Al[mt], al + o);
        }
#pragma unroll
        for (int nb = 0; nb < NB; nb++) {
            int row = wn * (16 * NB) + nb * 16 + (lane & 7) + ((lane & 16) ? 8 : 0);
            int cb = s * 32 + ((lane & 8) ? 16 : 0);
            uint32_t o = SW128((uint32_t)(row * 128 + cb));
            ldsm_x4(Bh[nb], bh + o);
            ldsm_x4(Bl[nb], bl + o);
        }
#pragma unroll
        for (int mt = 0; mt < MT; mt++)
#pragma unroll
            for (int nt = 0; nt < 2 * NB; nt++)
                mma16816(acc[mt][nt], Ah[mt], &Bh[nt >> 1][(nt & 1) * 2]);
#pragma unroll
        for (int mt = 0; mt < MT; mt++)
#pragma unroll
            for (int nt = 0; nt < 2 * NB; nt++)
                mma16816(acc[mt][nt], Ah[mt], &Bl[nt >> 1][(nt & 1) * 2]);
#pragma unroll
        for (int mt = 0; mt < MT; mt++)
#pragma unroll
            for (int nt = 0; nt < 2 * NB; nt++)
                mma16816(acc[mt][nt], Al[mt], &Bh[nt >> 1][(nt & 1) * 2]);
    }
}

// ---------------- gemmG tile prefetch (cp.async, 256 threads) ----------------
__device__ __forceinline__ void gemmG_load_stage(uint32_t sb, int t, int m0, int n0, int ktg) {
#pragma unroll
    for (int i = 0; i < 4; i++) {
        int idx = t + i * 256;
        int row = idx >> 3, q = idx & 7;
        uint32_t off = SW128((uint32_t)(row * 128 + q * 16));
        size_t src = (size_t)(m0 + row) * (H_DIM / 8) + (size_t)ktg * 8 + q;
        cpa16(sb + off,         &g_Chi4[src]);
        cpa16(sb + 16384 + off, &g_Clo4[src]);
    }
#pragma unroll
    for (int i = 0; i < 2; i++) {
        int idx = t + i * 256;
        int row = idx >> 3, q = idx & 7;
        uint32_t off = SW128((uint32_t)(row * 128 + q * 16));
        size_t src = (size_t)(n0 + row) * (H_DIM / 8) + (size_t)ktg * 8 + q;
        cpa16(sb + 32768 + off, &g_BwTh4[src]);
        cpa16(sb + 40960 + off, &g_BwTl4[src]);
    }
}

// ---------------- kernel 2: gemmG, single wave (280 CTAs) ----------------
__global__ __launch_bounds__(256, 2) void gemmG_kernel() {
    extern __shared__ __align__(128) char dsm[];
    uint32_t sb = smem_u32(dsm);
    int t = threadIdx.x, lane = t & 31, w = t >> 5;
    int wm = w >> 1, wn = w & 1;
    int n0 = blockIdx.x * 64, m0 = blockIdx.y * 128, sp = blockIdx.z;
    int kt0 = (128 * sp) / GSPLITS, kt1 = (128 * (sp + 1)) / GSPLITS;
    float acc[2][4][4];
#pragma unroll
    for (int mt = 0; mt < 2; mt++)
#pragma unroll
        for (int nt = 0; nt < 4; nt++)
#pragma unroll
            for (int e = 0; e < 4; e++) acc[mt][nt][e] = 0.0f;

    gemmG_load_stage(sb, t, m0, n0, kt0);
    CPA_COMMIT();
#pragma unroll 1
    for (int kt = kt0; kt < kt1; kt++) {
        __syncthreads();
        if (kt + 1 < kt1) {
            gemmG_load_stage(sb + ((kt - kt0 + 1) & 1) * STAGE_BYTES, t, m0, n0, kt + 1);
            CPA_COMMIT();
            asm volatile("cp.async.wait_group 1;" ::: "memory");
        } else {
            asm volatile("cp.async.wait_group 0;" ::: "memory");
        }
        __syncthreads();
        uint32_t ss = sb + ((kt - kt0) & 1) * STAGE_BYTES;
        mma3<2, 2>(lane, wm, wn, acc, ss, ss + 16384, ss + 32768, ss + 40960);
    }
    float* out = g_Gpart[sp];
    int gid = lane >> 2, tig = lane & 3;
#pragma unroll
    for (int mt = 0; mt < 2; mt++)
#pragma unroll
        for (int nt = 0; nt < 4; nt++) {
            int r0 = m0 + wm * 32 + mt * 16 + gid;
            int c = n0 + wn * 32 + nt * 8 + tig * 2;
            *(float2*)&out[(size_t)r0 * KIN + c] =
                make_float2(acc[mt][nt][0], acc[mt][nt][1]);
            *(float2*)&out[(size_t)(r0 + 8) * KIN + c] =
                make_float2(acc[mt][nt][2], acc[mt][nt][3]);
        }
}

// ---------------- kernel 3: split-K reduce -> G bf16 hi/lo + y0 ----------------
__global__ void reduceG_kernel() {
    int idx = blockIdx.x * blockDim.x + threadIdx.x;
    if (idx < Y_DIM * KIN) {
        float s = 0.0f;
#pragma unroll
        for (int p = 0; p < GSPLITS; p++) s += g_Gpart[p][idx];
        unsigned short hh, ll;
        split1(s, hh, ll);
        ((unsigned short*)g_Ghi4)[idx] = hh;
        ((unsigned short*)g_Glo4)[idx] = ll;
    }
    if (idx < Y_DIM) {
        g_y0[idx] = (g_y0p[idx * 4 + 0] + g_y0p[idx * 4 + 1]) +
                    (g_y0p[idx * 4 + 2] + g_y0p[idx * 4 + 3]);
    }
}

// ---------------- finalY tile prefetch (cp.async, 128 threads) ----------------
// stage: AH [0,8K) AL [8K,16K) BH [16K,24K) BL [24K,32K)
__device__ __forceinline__ void finalY_load_stage(uint32_t sb, int t, int m0, int n0, int kt) {
#pragma unroll
    for (int i = 0; i < 4; i++) {
        int idx = t + i * 128;
        int row = idx >> 3, q = idx & 7;
        uint32_t off = SW128((uint32_t)(row * 128 + q * 16));
        size_t sA = (size_t)(m0 + row) * (KIN / 8) + (size_t)kt * 8 + q;
        size_t sB = (size_t)(n0 + row) * (KIN / 8) + (size_t)kt * 8 + q;
        cpa16(sb + off,         &g_uduh4[sA]);
        cpa16(sb + 8192 + off,  &g_udul4[sA]);
        cpa16(sb + 16384 + off, &g_Ghi4[sB]);
        cpa16(sb + 24576 + off, &g_Glo4[sB]);
    }
}

// ---------------- kernel 4: finalY = y0 + udu @ G^T, double-buffered ----------------
// grid (4 n, 64 m) = 256 CTAs, 128 thr (4 warps, warp tile 32x32), 64KB dyn smem
__global__ __launch_bounds__(128) void finalY_kernel(float* __restrict__ y) {
    extern __shared__ __align__(128) char dsm[];
    uint32_t sb = smem_u32(dsm);
    int t = threadIdx.x, lane = t & 31, w = t >> 5;
    int wm = w >> 1, wn = w & 1;
    int n0 = blockIdx.x * 64, m0 = blockIdx.y * 64;
    float acc[2][4][4];
#pragma unroll
    for (int mt = 0; mt < 2; mt++)
#pragma unroll
        for (int nt = 0; nt < 4; nt++)
#pragma unroll
            for (int e = 0; e < 4; e++) acc[mt][nt][e] = 0.0f;

    finalY_load_stage(sb, t, m0, n0, 0);
    CPA_COMMIT();
#pragma unroll 1
    for (int kt = 0; kt < KIN / 64; kt++) {
        __syncthreads();
        if (kt + 1 < KIN / 64) {
            finalY_load_stage(sb + ((kt + 1) & 1) * FY_STAGE, t, m0, n0, kt + 1);
            CPA_COMMIT();
            asm volatile("cp.async.wait_group 1;" ::: "memory");
        } else {
            asm volatile("cp.async.wait_group 0;" ::: "memory");
        }
        __syncthreads();
        uint32_t ss = sb + (kt & 1) * FY_STAGE;
        mma3<2, 2>(lane, wm, wn, acc, ss, ss + 8192, ss + 16384, ss + 24576);
    }
    int gid = lane >> 2, tig = lane & 3;
#pragma unroll
    for (int mt = 0; mt < 2; mt++)
#pragma unroll
        for (int nt = 0; nt < 4; nt++) {
            int r0 = m0 + wm * 32 + mt * 16 + gid;
            int c = n0 + wn * 32 + nt * 8 + tig * 2;
            float2 y0v = *(const float2*)&g_y0[c];
            *(float2*)&y[(size_t)r0 * Y_DIM + c] =
                make_float2(acc[mt][nt][0] + y0v.x, acc[mt][nt][1] + y0v.y);
            *(float2*)&y[(size_t)(r0 + 8) * Y_DIM + c] =
                make_float2(acc[mt][nt][2] + y0v.x, acc[mt][nt][3] + y0v.y);
        }
}

// ---------------- launch ----------------
extern "C" void kernel_launch(void* const* d_in, const int* in_sizes, int n_in,
                              void* d_out, int out_size) {
    const float *u = nullptr, *du = nullptr, *h = nullptr, *om = nullptr,
                *Bw = nullptr, *Cw = nullptr;
    for (int i = 0; i < n_in; i++) {
        switch (in_sizes[i]) {
            case B_N * U_DIM:   u  = (const float*)d_in[i]; break;
            case B_N * D_DIM:   du = (const float*)d_in[i]; break;
            case H_DIM:         h  = (const float*)d_in[i]; break;
            case ORD:           om = (const float*)d_in[i]; break;
            case H_DIM * KIN:   Bw = (const float*)d_in[i]; break;
            case Y_DIM * H_DIM: Cw = (const float*)d_in[i]; break;
            default: break;
        }
    }
    if (!u || !du || !h || !om || !Bw || !Cw) {
        u  = (const float*)d_in[0];
        du = (const float*)d_in[1];
        h  = (const float*)d_in[2];
        om = (const float*)d_in[3];
        Bw = (const float*)d_in[4];
        Cw = (const float*)d_in[5];
    }
    float* y = (float*)d_out;

    cudaFuncSetAttribute(gemmG_kernel,
                         cudaFuncAttributeMaxDynamicSharedMemorySize, 2 * STAGE_BYTES);
    cudaFuncSetAttribute(finalY_kernel,
                         cudaFuncAttributeMaxDynamicSharedMemorySize, 2 * FY_STAGE);

    prepare_kernel<<<2304, 256>>>(Cw, Bw, u, du, om, h);
    gemmG_kernel<<<dim3(5, 2, GSPLITS), 256, 2 * STAGE_BYTES>>>();
    reduceG_kernel<<<(Y_DIM * KIN + 255) / 256, 256>>>();
    finalY_kernel<<<dim3(Y_DIM / 64, B_N / 64), 128, 2 * FY_STAGE>>>(y);
}

// round 16
// speedup vs baseline: 1.1858x; 1.0491x over previous
#include <cuda_runtime.h>
#include <cuda_bf16.h>
#include <cstdint>

// Problem dims
#define B_N    4096
#define U_DIM  256
#define D_DIM  64
#define KIN    320
#define H_DIM  8192
#define ORD    4096
#define Y_DIM  256
#define DELTA_F 0.1f

#define GSPLITS 28            // grid 5*2*28 = 280 CTAs = one clean 2-CTA/SM wave
#define STAGE_BYTES 49152
#define FY_STAGE 32768

// ---------------- scratch (static device globals) ----------------
__device__ uint4 g_Chi4[Y_DIM * H_DIM / 8];   // C' hi bf16 [256][8192]
__device__ uint4 g_Clo4[Y_DIM * H_DIM / 8];
__device__ uint4 g_BwTh4[KIN * H_DIM / 8];    // Bw^T hi bf16 [320][8192]
__device__ uint4 g_BwTl4[KIN * H_DIM / 8];
__device__ uint4 g_uduh4[B_N * KIN / 8];      // [du|u] hi bf16 [4096][320]
__device__ uint4 g_udul4[B_N * KIN / 8];
__device__ float g_Gpart[GSPLITS][Y_DIM * KIN];
__device__ uint4 g_Ghi4[Y_DIM * KIN / 8];     // G hi bf16 [256][320]
__device__ uint4 g_Glo4[Y_DIM * KIN / 8];
__device__ float g_y0p[Y_DIM * 4], g_y0[Y_DIM];

// ---------------- helpers ----------------
__device__ __forceinline__ uint32_t smem_u32(const void* p) {
    uint32_t a;
    asm("{ .reg .u64 t; cvta.to.shared.u64 t, %1; cvt.u32.u64 %0, t; }"
        : "=r"(a) : "l"(p));
    return a;
}
#define SW128(o) ((o) ^ (((o) >> 3) & 0x70))

__device__ __forceinline__ void ldsm_x4(uint32_t* r, uint32_t addr) {
    asm volatile("ldmatrix.sync.aligned.m8n8.x4.shared.b16 {%0,%1,%2,%3}, [%4];"
                 : "=r"(r[0]), "=r"(r[1]), "=r"(r[2]), "=r"(r[3]) : "r"(addr));
}
__device__ __forceinline__ void mma16816(float* c, const uint32_t* a, const uint32_t* b) {
    asm volatile(
        "mma.sync.aligned.m16n8k16.row.col.f32.bf16.bf16.f32 "
        "{%0,%1,%2,%3}, {%4,%5,%6,%7}, {%8,%9}, {%0,%1,%2,%3};"
        : "+f"(c[0]), "+f"(c[1]), "+f"(c[2]), "+f"(c[3])
        : "r"(a[0]), "r"(a[1]), "r"(a[2]), "r"(a[3]), "r"(b[0]), "r"(b[1]));
}
__device__ __forceinline__ void cpa16(uint32_t s, const void* g) {
    asm volatile("cp.async.cg.shared.global [%0], [%1], 16;" :: "r"(s), "l"(g) : "memory");
}
#define CPA_COMMIT() asm volatile("cp.async.commit_group;" ::: "memory")

__device__ __forceinline__ void split1(float v, unsigned short& h, unsigned short& l) {
    __nv_bfloat16 hb = __float2bfloat16(v);
    float r = v - __bfloat162float(hb);
    __nv_bfloat16 lb = __float2bfloat16(r);
    h = *reinterpret_cast<unsigned short*>(&hb);
    l = *reinterpret_cast<unsigned short*>(&lb);
}
__device__ __forceinline__ uint32_t pkw(unsigned short a, unsigned short b) {
    return (uint32_t)a | ((uint32_t)b << 16);
}

// ---------------- kernel 1: unified prepare ----------------
// blocks [0,1024): C' fold + y0 partials (coef inlined)
// blocks [1024,1664): Bw transpose + split
// blocks [1664,2304): udu concat + split
__global__ __launch_bounds__(256) void prepare_kernel(const float* __restrict__ Cw,
                                                      const float* __restrict__ Bw,
                                                      const float* __restrict__ u,
                                                      const float* __restrict__ du,
                                                      const float* __restrict__ om,
                                                      const float* __restrict__ hst) {
    __shared__ __align__(16) char shmem[64 * 65 * 4];
    int bid = blockIdx.x;
    int t = threadIdx.x;
    if (bid < 1024) {
        int m = bid >> 2;
        int jb = (bid & 3) * 1024 + t * 4;      // 4 pairs = 8 elems
        float4 wv = *(const float4*)(om + jb);
        float p[4], q[4], rc[8];
        float4 h0 = *(const float4*)(hst + 2 * jb);
        float4 h1 = *(const float4*)(hst + 2 * jb + 4);
        float hh[8] = {h0.x, h0.y, h0.z, h0.w, h1.x, h1.y, h1.z, h1.w};
        float wa[4] = {wv.x, wv.y, wv.z, wv.w};
#pragma unroll
        for (int i = 0; i < 4; i++) {
            float s, c;
            sincosf(wa[i] * DELTA_F, &s, &c);
            float inv = 1.0f / wa[i];
            p[i] = s * inv;
            q[i] = (c - 1.0f) * inv;
            rc[2 * i]     =  c * hh[2 * i] + s * hh[2 * i + 1];
            rc[2 * i + 1] = -s * hh[2 * i] + c * hh[2 * i + 1];
        }
        const float* crow = Cw + (size_t)m * H_DIM;
        float4 c0 = *(const float4*)(crow + 2 * jb);
        float4 c1 = *(const float4*)(crow + 2 * jb + 4);
        float cc[8] = {c0.x, c0.y, c0.z, c0.w, c1.x, c1.y, c1.z, c1.w};
        float y0acc = 0.0f;
        float o[8];
#pragma unroll
        for (int i = 0; i < 4; i++) {
            y0acc += cc[2 * i] * rc[2 * i] + cc[2 * i + 1] * rc[2 * i + 1];
            o[2 * i]     =  cc[2 * i] * p[i] + cc[2 * i + 1] * q[i];
            o[2 * i + 1] = -cc[2 * i] * q[i] + cc[2 * i + 1] * p[i];
        }
        unsigned short h[8], l[8];
#pragma unroll
        for (int i = 0; i < 8; i++) split1(o[i], h[i], l[i]);
        size_t vi = ((size_t)m * H_DIM + 2 * jb) / 8;
        g_Chi4[vi] = make_uint4(pkw(h[0], h[1]), pkw(h[2], h[3]), pkw(h[4], h[5]), pkw(h[6], h[7]));
        g_Clo4[vi] = make_uint4(pkw(l[0], l[1]), pkw(l[2], l[3]), pkw(l[4], l[5]), pkw(l[6], l[7]));
        float* red = (float*)shmem;
        red[t] = y0acc;
        __syncthreads();
        for (int off = 128; off > 0; off >>= 1) {
            if (t < off) red[t] += red[t + off];
            __syncthreads();
        }
        if (t == 0) g_y0p[m * 4 + (bid & 3)] = red[0];
    } else if (bid < 1664) {
        int b = bid - 1024;
        int k0 = (b & 127) * 64, n0 = (b >> 7) * 64;
        float (*tile)[65] = (float(*)[65])shmem;
#pragma unroll
        for (int i = 0; i < 4; i++) {
            int idx = t + i * 256;
            int r = idx >> 4, c4 = idx & 15;
            float4 v = *(const float4*)&Bw[(size_t)(k0 + r) * KIN + n0 + c4 * 4];
            tile[r][c4 * 4 + 0] = v.x;
            tile[r][c4 * 4 + 1] = v.y;
            tile[r][c4 * 4 + 2] = v.z;
            tile[r][c4 * 4 + 3] = v.w;
        }
        __syncthreads();
#pragma unroll
        for (int i = 0; i < 2; i++) {
            int idx = t + i * 256;
            int nr = idx >> 3, q = idx & 7;
            unsigned short h[8], l[8];
#pragma unroll
            for (int e = 0; e < 8; e++) split1(tile[q * 8 + e][nr], h[e], l[e]);
            size_t vi = ((size_t)(n0 + nr) * H_DIM + k0 + q * 8) / 8;
            g_BwTh4[vi] = make_uint4(pkw(h[0], h[1]), pkw(h[2], h[3]), pkw(h[4], h[5]), pkw(h[6], h[7]));
            g_BwTl4[vi] = make_uint4(pkw(l[0], l[1]), pkw(l[2], l[3]), pkw(l[4], l[5]), pkw(l[6], l[7]));
        }
    } else {
        int idx8 = (bid - 1664) * 256 + t;
        if (idx8 >= B_N * KIN / 8) return;
        int row = idx8 / (KIN / 8);
        int col = (idx8 % (KIN / 8)) * 8;
        float4 v0, v1;
        if (col < D_DIM) {
            v0 = *(const float4*)&du[(size_t)row * D_DIM + col];
            v1 = *(const float4*)&du[(size_t)row * D_DIM + col + 4];
        } else {
            v0 = *(const float4*)&u[(size_t)row * U_DIM + col - D_DIM];
            v1 = *(const float4*)&u[(size_t)row * U_DIM + col - D_DIM + 4];
        }
        unsigned short h[8], l[8];
        split1(v0.x, h[0], l[0]); split1(v0.y, h[1], l[1]);
        split1(v0.z, h[2], l[2]); split1(v0.w, h[3], l[3]);
        split1(v1.x, h[4], l[4]); split1(v1.y, h[5], l[5]);
        split1(v1.z, h[6], l[6]); split1(v1.w, h[7], l[7]);
        g_uduh4[idx8] = make_uint4(pkw(h[0], h[1]), pkw(h[2], h[3]), pkw(h[4], h[5]), pkw(h[6], h[7]));
        g_udul4[idx8] = make_uint4(pkw(l[0], l[1]), pkw(l[2], l[3]), pkw(l[4], l[5]), pkw(l[6], l[7]));
    }
}

// ---------------- shared mma core: 3-term split, term-major, s-range ----------------
// SC = number of k16 s-steps handled (sbase..sbase+SC-1).
template <int MT, int NB, int SC>
__device__ __forceinline__ void mma3(int lane, int wm, int wn, int sbase,
                                     float acc[][2 * NB][4],
                                     uint32_t ah, uint32_t al,
                                     uint32_t bh, uint32_t bl) {
#pragma unroll
    for (int si = 0; si < SC; si++) {
        int s = sbase + si;
        uint32_t Ah[MT][4], Al[MT][4], Bh[NB][4], Bl[NB][4];
#pragma unroll
        for (int mt = 0; mt < MT; mt++) {
            int row = wm * (16 * MT) + mt * 16 + (lane & 15);
            int cb = s * 32 + ((lane >> 4) << 4);
            uint32_t o = SW128((uint32_t)(row * 128 + cb));
            ldsm_x4(Ah[mt], ah + o);
            ldsm_x4(Al[mt], al + o);
        }
#pragma unroll
        for (int nb = 0; nb < NB; nb++) {
            int row = wn * (16 * NB) + nb * 16 + (lane & 7) + ((lane & 16) ? 8 : 0);
            int cb = s * 32 + ((lane & 8) ? 16 : 0);
            uint32_t o = SW128((uint32_t)(row * 128 + cb));
            ldsm_x4(Bh[nb], bh + o);
            ldsm_x4(Bl[nb], bl + o);
        }
#pragma unroll
        for (int mt = 0; mt < MT; mt++)
#pragma unroll
            for (int nt = 0; nt < 2 * NB; nt++)
                mma16816(acc[mt][nt], Ah[mt], &Bh[nt >> 1][(nt & 1) * 2]);
#pragma unroll
        for (int mt = 0; mt < MT; mt++)
#pragma unroll
            for (int nt = 0; nt < 2 * NB; nt++)
                mma16816(acc[mt][nt], Ah[mt], &Bl[nt >> 1][(nt & 1) * 2]);
#pragma unroll
        for (int mt = 0; mt < MT; mt++)
#pragma unroll
            for (int nt = 0; nt < 2 * NB; nt++)
                mma16816(acc[mt][nt], Al[mt], &Bh[nt >> 1][(nt & 1) * 2]);
    }
}

// ---------------- gemmG tile prefetch (cp.async, 256 threads) ----------------
__device__ __forceinline__ void gemmG_load_stage(uint32_t sb, int t, int m0, int n0, int ktg) {
#pragma unroll
    for (int i = 0; i < 4; i++) {
        int idx = t + i * 256;
        int row = idx >> 3, q = idx & 7;
        uint32_t off = SW128((uint32_t)(row * 128 + q * 16));
        size_t src = (size_t)(m0 + row) * (H_DIM / 8) + (size_t)ktg * 8 + q;
        cpa16(sb + off,         &g_Chi4[src]);
        cpa16(sb + 16384 + off, &g_Clo4[src]);
    }
#pragma unroll
    for (int i = 0; i < 2; i++) {
        int idx = t + i * 256;
        int row = idx >> 3, q = idx & 7;
        uint32_t off = SW128((uint32_t)(row * 128 + q * 16));
        size_t src = (size_t)(n0 + row) * (H_DIM / 8) + (size_t)ktg * 8 + q;
        cpa16(sb + 32768 + off, &g_BwTh4[src]);
        cpa16(sb + 40960 + off, &g_BwTl4[src]);
    }
}

// ---------------- kernel 2: gemmG, single wave (280 CTAs) ----------------
__global__ __launch_bounds__(256, 2) void gemmG_kernel() {
    extern __shared__ __align__(128) char dsm[];
    uint32_t sb = smem_u32(dsm);
    int t = threadIdx.x, lane = t & 31, w = t >> 5;
    int wm = w >> 1, wn = w & 1;
    int n0 = blockIdx.x * 64, m0 = blockIdx.y * 128, sp = blockIdx.z;
    int kt0 = (128 * sp) / GSPLITS, kt1 = (128 * (sp + 1)) / GSPLITS;
    float acc[2][4][4];
#pragma unroll
    for (int mt = 0; mt < 2; mt++)
#pragma unroll
        for (int nt = 0; nt < 4; nt++)
#pragma unroll
            for (int e = 0; e < 4; e++) acc[mt][nt][e] = 0.0f;

    gemmG_load_stage(sb, t, m0, n0, kt0);
    CPA_COMMIT();
#pragma unroll 1
    for (int kt = kt0; kt < kt1; kt++) {
        __syncthreads();
        if (kt + 1 < kt1) {
            gemmG_load_stage(sb + ((kt - kt0 + 1) & 1) * STAGE_BYTES, t, m0, n0, kt + 1);
            CPA_COMMIT();
            asm volatile("cp.async.wait_group 1;" ::: "memory");
        } else {
            asm volatile("cp.async.wait_group 0;" ::: "memory");
        }
        __syncthreads();
        uint32_t ss = sb + ((kt - kt0) & 1) * STAGE_BYTES;
        mma3<2, 2, 4>(lane, wm, wn, 0, acc, ss, ss + 16384, ss + 32768, ss + 40960);
    }
    float* out = g_Gpart[sp];
    int gid = lane >> 2, tig = lane & 3;
#pragma unroll
    for (int mt = 0; mt < 2; mt++)
#pragma unroll
        for (int nt = 0; nt < 4; nt++) {
            int r0 = m0 + wm * 32 + mt * 16 + gid;
            int c = n0 + wn * 32 + nt * 8 + tig * 2;
            *(float2*)&out[(size_t)r0 * KIN + c] =
                make_float2(acc[mt][nt][0], acc[mt][nt][1]);
            *(float2*)&out[(size_t)(r0 + 8) * KIN + c] =
                make_float2(acc[mt][nt][2], acc[mt][nt][3]);
        }
}

// ---------------- kernel 3: split-K reduce -> G bf16 hi/lo + y0 ----------------
__global__ void reduceG_kernel() {
    int idx = blockIdx.x * blockDim.x + threadIdx.x;
    if (idx < Y_DIM * KIN) {
        float s = 0.0f;
#pragma unroll
        for (int p = 0; p < GSPLITS; p++) s += g_Gpart[p][idx];
        unsigned short hh, ll;
        split1(s, hh, ll);
        ((unsigned short*)g_Ghi4)[idx] = hh;
        ((unsigned short*)g_Glo4)[idx] = ll;
    }
    if (idx < Y_DIM) {
        g_y0[idx] = (g_y0p[idx * 4 + 0] + g_y0p[idx * 4 + 1]) +
                    (g_y0p[idx * 4 + 2] + g_y0p[idx * 4 + 3]);
    }
}

// ---------------- finalY tile prefetch (cp.async, 256 threads) ----------------
// stage: AH [0,8K) AL [8K,16K) BH [16K,24K) BL [24K,32K)
__device__ __forceinline__ void finalY_load_stage(uint32_t sb, int t, int m0, int n0, int kt) {
#pragma unroll
    for (int i = 0; i < 2; i++) {
        int idx = t + i * 256;
        int row = idx >> 3, q = idx & 7;
        uint32_t off = SW128((uint32_t)(row * 128 + q * 16));
        size_t sA = (size_t)(m0 + row) * (KIN / 8) + (size_t)kt * 8 + q;
        size_t sB = (size_t)(n0 + row) * (KIN / 8) + (size_t)kt * 8 + q;
        cpa16(sb + off,         &g_uduh4[sA]);
        cpa16(sb + 8192 + off,  &g_udul4[sA]);
        cpa16(sb + 16384 + off, &g_Ghi4[sB]);
        cpa16(sb + 24576 + off, &g_Glo4[sB]);
    }
}

// ---------------- kernel 4: finalY = y0 + udu @ G^T, 256 thr, in-CTA k-split ----------------
// grid (4 n, 64 m) = 256 CTAs, 8 warps: (wm,wn,wk); warp tile 32x32, wk splits s 0-1 / 2-3.
// 64KB dyn smem (2 stages); cross-k reduction through 16KB of stage 0 after the mainloop.
__global__ __launch_bounds__(256) void finalY_kernel(float* __restrict__ y) {
    extern __shared__ __align__(128) char dsm[];
    uint32_t sb = smem_u32(dsm);
    int t = threadIdx.x, lane = t & 31, w = t >> 5;
    int wm = (w >> 1) & 1, wn = w & 1, wk = w >> 2;
    int n0 = blockIdx.x * 64, m0 = blockIdx.y * 64;
    float acc[2][4][4];
#pragma unroll
    for (int mt = 0; mt < 2; mt++)
#pragma unroll
        for (int nt = 0; nt < 4; nt++)
#pragma unroll
            for (int e = 0; e < 4; e++) acc[mt][nt][e] = 0.0f;

    finalY_load_stage(sb, t, m0, n0, 0);
    CPA_COMMIT();
#pragma unroll 1
    for (int kt = 0; kt < KIN / 64; kt++) {
        __syncthreads();
        if (kt + 1 < KIN / 64) {
            finalY_load_stage(sb + ((kt + 1) & 1) * FY_STAGE, t, m0, n0, kt + 1);
            CPA_COMMIT();
            asm volatile("cp.async.wait_group 1;" ::: "memory");
        } else {
            asm volatile("cp.async.wait_group 0;" ::: "memory");
        }
        __syncthreads();
        uint32_t ss = sb + (kt & 1) * FY_STAGE;
        mma3<2, 2, 2>(lane, wm, wn, wk * 2, acc, ss, ss + 8192, ss + 16384, ss + 24576);
    }
    // cross-k-half reduction: wk==1 warps publish, wk==0 warps combine (fixed order).
    __syncthreads();
    float* red = (float*)dsm;                 // reuse stage 0 (16 KB)
    int pos = (wm * 2 + wn) * 32 + lane;      // 0..127, lane-consecutive
    if (wk == 1) {
#pragma unroll
        for (int mt = 0; mt < 2; mt++)
#pragma unroll
            for (int nt = 0; nt < 4; nt++)
#pragma unroll
                for (int e = 0; e < 4; e++)
                    red[(mt * 16 + nt * 4 + e) * 128 + pos] = acc[mt][nt][e];
    }
    __syncthreads();
    if (wk == 0) {
        int gid = lane >> 2, tig = lane & 3;
#pragma unroll
        for (int mt = 0; mt < 2; mt++)
#pragma unroll
            for (int nt = 0; nt < 4; nt++)
#pragma unroll
                for (int e = 0; e < 4; e++)
                    acc[mt][nt][e] += red[(mt * 16 + nt * 4 + e) * 128 + pos];
#pragma unroll
        for (int mt = 0; mt < 2; mt++)
#pragma unroll
            for (int nt = 0; nt < 4; nt++) {
                int r0 = m0 + wm * 32 + mt * 16 + gid;
                int c = n0 + wn * 32 + nt * 8 + tig * 2;
                float2 y0v = *(const float2*)&g_y0[c];
                *(float2*)&y[(size_t)r0 * Y_DIM + c] =
                    make_float2(acc[mt][nt][0] + y0v.x, acc[mt][nt][1] + y0v.y);
                *(float2*)&y[(size_t)(r0 + 8) * Y_DIM + c] =
                    make_float2(acc[mt][nt][2] + y0v.x, acc[mt][nt][3] + y0v.y);
            }
    }
}

// ---------------- launch ----------------
extern "C" void kernel_launch(void* const* d_in, const int* in_sizes, int n_in,
                              void* d_out, int out_size) {
    const float *u = nullptr, *du = nullptr, *h = nullptr, *om = nullptr,
                *Bw = nullptr, *Cw = nullptr;
    for (int i = 0; i < n_in; i++) {
        switch (in_sizes[i]) {
            case B_N * U_DIM:   u  = (const float*)d_in[i]; break;
            case B_N * D_DIM:   du = (const float*)d_in[i]; break;
            case H_DIM:         h  = (const float*)d_in[i]; break;
            case ORD:           om = (const float*)d_in[i]; break;
            case H_DIM * KIN:   Bw = (const float*)d_in[i]; break;
            case Y_DIM * H_DIM: Cw = (const float*)d_in[i]; break;
            default: break;
        }
    }
    if (!u || !du || !h || !om || !Bw || !Cw) {
        u  = (const float*)d_in[0];
        du = (const float*)d_in[1];
        h  = (const float*)d_in[2];
        om = (const float*)d_in[3];
        Bw = (const float*)d_in[4];
        Cw = (const float*)d_in[5];
    }
    float* y = (float*)d_out;

    cudaFuncSetAttribute(gemmG_kernel,
                         cudaFuncAttributeMaxDynamicSharedMemorySize, 2 * STAGE_BYTES);
    cudaFuncSetAttribute(finalY_kernel,
                         cudaFuncAttributeMaxDynamicSharedMemorySize, 2 * FY_STAGE);

    prepare_kernel<<<2304, 256>>>(Cw, Bw, u, du, om, h);
    gemmG_kernel<<<dim3(5, 2, GSPLITS), 256, 2 * STAGE_BYTES>>>();
    reduceG_kernel<<<(Y_DIM * KIN + 255) / 256, 256>>>();
    finalY_kernel<<<dim3(Y_DIM / 64, B_N / 64), 256, 2 * FY_STAGE>>>(y);
}